// round 1
// baseline (speedup 1.0000x reference)
#include <cuda_runtime.h>
#include <math.h>

#define NB 1024
#define ND 8
#define NP 128
#define NPTS 1024
#define NT 256
#define PPT 4

// ---- output offsets (elements, f32), outputs concatenated in return order ----
#define O_NX   0u
#define O_NXD  3072u
#define O_NQ   6144u
#define O_NOM  10240u
#define O_NTH  13312u
#define O_XDD  21504u
#define O_OMD  24576u
#define O_THD  27648u
#define O_FS   35840u
#define O_FF   3181568u
#define O_IC   6327296u
#define O_TQ   7375872u
#define O_RP   7378944u
#define O_THR  10524672u
// total = 13670400

__device__ __forceinline__ float clampf(float v, float lo, float hi){
    return fminf(fmaxf(v, lo), hi);
}

__global__ __launch_bounds__(NT) void phys_kernel(
    const float* __restrict__ g_x, const float* __restrict__ g_xd,
    const float* __restrict__ g_q, const float* __restrict__ g_om,
    const float* __restrict__ g_th, const float* __restrict__ g_ctl,
    const float* __restrict__ g_zg, const float* __restrict__ g_zgg,
    const float* __restrict__ g_jpos, const float* __restrict__ g_jlp,
    const float* __restrict__ g_jlc, const float* __restrict__ g_dpi,
    const float* __restrict__ g_dpm, const float* __restrict__ g_bcog,
    const float* __restrict__ g_bin, const float* __restrict__ g_dd,
    float* __restrict__ out)
{
    const int b = blockIdx.x;
    const int tid = threadIdx.x;
    const int lane = tid & 31;
    const int wid = tid >> 5;

    __shared__ float sR[9];
    __shared__ float s_rot[ND][9];
    __shared__ float s_jp[ND][3];
    __shared__ float s_thr[ND][3];
    __shared__ float s_cogl[ND][3];
    __shared__ float s_RI[ND][9];
    __shared__ float s_gcog[3], s_gdd[3], s_I[9];
    __shared__ float s_x[3], s_xd[3], s_om[3], s_q[4];
    __shared__ float s_tm, s_nc, s_kd;
    __shared__ float s_red[8][6];

    // ---------------- phase 0: per-d precompute (threads 0..7) ----------------
    if (tid < ND) {
        const int d = tid;
        float qw=g_q[b*4+0], qx=g_q[b*4+1], qy=g_q[b*4+2], qz=g_q[b*4+3];
        float R0=1.f-2.f*(qy*qy+qz*qz), R1=2.f*(qx*qy-qw*qz), R2=2.f*(qx*qz+qw*qy);
        float R3=2.f*(qx*qy+qw*qz), R4=1.f-2.f*(qx*qx+qz*qz), R5=2.f*(qy*qz-qw*qx);
        float R6=2.f*(qx*qz-qw*qy), R7=2.f*(qy*qz+qw*qx), R8=1.f-2.f*(qx*qx+qy*qy);
        float th = g_th[b*ND+d];
        float c=cosf(th), s=sinf(th);
        float r0=c, r2=s, r6=-s, r8=c;
        s_rot[d][0]=r0; s_rot[d][1]=0.f; s_rot[d][2]=r2;
        s_rot[d][3]=0.f; s_rot[d][4]=1.f; s_rot[d][5]=0.f;
        s_rot[d][6]=r6; s_rot[d][7]=0.f; s_rot[d][8]=r8;
        float jp0=g_jpos[d*3], jp1=g_jpos[d*3+1], jp2=g_jpos[d*3+2];
        s_jp[d][0]=jp0; s_jp[d][1]=jp1; s_jp[d][2]=jp2;
        float c0=g_jlc[d*3], c1=g_jlc[d*3+1], c2=g_jlc[d*3+2];
        s_cogl[d][0]=r0*c0+r2*c2+jp0;
        s_cogl[d][1]=c1+jp1;
        s_cogl[d][2]=r6*c0+r8*c2+jp2;
        // rot * I * rot^T (rot is y-rotation; zeros contribute exactly 0)
        float I0=g_dpi[d*9+0],I1=g_dpi[d*9+1],I2=g_dpi[d*9+2];
        float I3=g_dpi[d*9+3],I4=g_dpi[d*9+4],I5=g_dpi[d*9+5];
        float I6=g_dpi[d*9+6],I7=g_dpi[d*9+7],I8=g_dpi[d*9+8];
        float T0=r0*I0+r2*I6, T1=r0*I1+r2*I7, T2=r0*I2+r2*I8;
        float T3=I3,          T4=I4,          T5=I5;
        float T6=r6*I0+r8*I6, T7=r6*I1+r8*I7, T8=r6*I2+r8*I8;
        s_RI[d][0]=T0*r0+T2*r2; s_RI[d][1]=T1;  s_RI[d][2]=T0*r6+T2*r8;
        s_RI[d][3]=T3*r0+T5*r2; s_RI[d][4]=T4;  s_RI[d][5]=T3*r6+T5*r8;
        s_RI[d][6]=T6*r0+T8*r2; s_RI[d][7]=T7;  s_RI[d][8]=T6*r6+T8*r8;
        float dd0=g_dd[0], dd1=g_dd[1], dd2=g_dd[2];
        float ctl=g_ctl[b*16+d];
        float tl0=(r0*dd0+r2*dd2)*ctl;
        float tl1=dd1*ctl;
        float tl2=(r6*dd0+r8*dd2)*ctl;
        s_thr[d][0]=R0*tl0+R1*tl1+R2*tl2;
        s_thr[d][1]=R3*tl0+R4*tl1+R5*tl2;
        s_thr[d][2]=R6*tl0+R7*tl1+R8*tl2;
        if (d==0) {
            sR[0]=R0;sR[1]=R1;sR[2]=R2;sR[3]=R3;sR[4]=R4;sR[5]=R5;sR[6]=R6;sR[7]=R7;sR[8]=R8;
            s_x[0]=g_x[b*3];s_x[1]=g_x[b*3+1];s_x[2]=g_x[b*3+2];
            s_xd[0]=g_xd[b*3];s_xd[1]=g_xd[b*3+1];s_xd[2]=g_xd[b*3+2];
            s_om[0]=g_om[b*3];s_om[1]=g_om[b*3+1];s_om[2]=g_om[b*3+2];
            s_q[0]=qw;s_q[1]=qx;s_q[2]=qy;s_q[3]=qz;
            s_gdd[0]=R0*dd0+R1*dd1+R2*dd2;
            s_gdd[1]=R3*dd0+R4*dd1+R5*dd2;
            s_gdd[2]=R6*dd0+R7*dd1+R8*dd2;
        }
        // theta outputs (independent of everything else)
        float ctl2 = g_ctl[b*16+ND+d];
        float td = clampf(ctl2, -0.5f, 0.5f);
        out[O_THD + (size_t)b*ND + d] = td;
        out[O_NTH + (size_t)b*ND + d] = clampf(th + td*0.01f, -1.f, 1.f);
    }
    __syncthreads();

    // ---------------- phase 0b: batch-level assembly (thread 0) ----------------
    if (tid == 0) {
        float m[ND]; float tm=40.f;
        float co0=0.f,co1=0.f,co2=0.f;
        #pragma unroll
        for (int d=0; d<ND; d++){
            m[d]=g_dpm[d]; tm+=m[d];
            co0+=s_cogl[d][0]*m[d]; co1+=s_cogl[d][1]*m[d]; co2+=s_cogl[d][2]*m[d];
        }
        float bc0=g_bcog[0],bc1=g_bcog[1],bc2=g_bcog[2];
        co0=(co0+40.f*bc0)/tm; co1=(co1+40.f*bc1)/tm; co2=(co2+40.f*bc2)/tm;
        float Io[9]={0,0,0,0,0,0,0,0,0};
        #pragma unroll
        for (int d=0; d<ND; d++){
            float d0=s_cogl[d][0]-co0, d1=s_cogl[d][1]-co1, d2=s_cogl[d][2]-co2;
            float ds=d0*d0+d1*d1+d2*d2;
            Io[0]+=s_RI[d][0]+m[d]*(ds-d0*d0);
            Io[1]+=s_RI[d][1]-m[d]*d0*d1;
            Io[2]+=s_RI[d][2]-m[d]*d0*d2;
            Io[3]+=s_RI[d][3]-m[d]*d0*d1;
            Io[4]+=s_RI[d][4]+m[d]*(ds-d1*d1);
            Io[5]+=s_RI[d][5]-m[d]*d1*d2;
            Io[6]+=s_RI[d][6]-m[d]*d0*d2;
            Io[7]+=s_RI[d][7]-m[d]*d1*d2;
            Io[8]+=s_RI[d][8]+m[d]*(ds-d2*d2);
        }
        float db0=bc0-co0, db1=bc1-co1, db2=bc2-co2;
        float dbs=db0*db0+db1*db1+db2*db2;
        Io[0]+=g_bin[0]+40.f*(dbs-db0*db0);
        Io[1]+=g_bin[1]-40.f*db0*db1;
        Io[2]+=g_bin[2]-40.f*db0*db2;
        Io[3]+=g_bin[3]-40.f*db0*db1;
        Io[4]+=g_bin[4]+40.f*(dbs-db1*db1);
        Io[5]+=g_bin[5]-40.f*db1*db2;
        Io[6]+=g_bin[6]-40.f*db0*db2;
        Io[7]+=g_bin[7]-40.f*db1*db2;
        Io[8]+=g_bin[8]+40.f*(dbs-db2*db2);
        // world inertia = R * Io * R^T
        float T[9];
        #pragma unroll
        for (int i=0;i<3;i++){
            T[i*3+0]=sR[i*3+0]*Io[0]+sR[i*3+1]*Io[3]+sR[i*3+2]*Io[6];
            T[i*3+1]=sR[i*3+0]*Io[1]+sR[i*3+1]*Io[4]+sR[i*3+2]*Io[7];
            T[i*3+2]=sR[i*3+0]*Io[2]+sR[i*3+1]*Io[5]+sR[i*3+2]*Io[8];
        }
        #pragma unroll
        for (int i=0;i<3;i++)
            #pragma unroll
            for (int j=0;j<3;j++)
                s_I[i*3+j]=T[i*3+0]*sR[j*3+0]+T[i*3+1]*sR[j*3+1]+T[i*3+2]*sR[j*3+2];
        s_gcog[0]=sR[0]*co0+sR[1]*co1+sR[2]*co2+s_x[0];
        s_gcog[1]=sR[3]*co0+sR[4]*co1+sR[5]*co2+s_x[1];
        s_gcog[2]=sR[6]*co0+sR[7]*co1+sR[8]*co2+s_x[2];
        s_tm=tm;
    }
    __syncthreads();

    // ---------------- phase 1: per-point geometry + contact ----------------
    float rp0[PPT],rp1[PPT],rp2[PPT];
    float n0a[PPT],n1a[PPT],n2a[PPT];
    float dha[PPT],ica[PPT];
    const float* zg  = g_zg  + (size_t)b*65536u;
    const float* gxg = g_zgg + (size_t)b*131072u;
    const float* gyg = gxg + 65536;
    float icsum=0.f;
    #pragma unroll
    for (int k=0;k<PPT;k++){
        const int p = tid + k*NT;
        const int d = p >> 7;
        const float* lp = g_jlp + ((size_t)(d*NP + (p & 127)))*3;
        float l0=__ldg(lp), l1=__ldg(lp+1), l2=__ldg(lp+2);
        float p0=s_rot[d][0]*l0+s_rot[d][2]*l2+s_jp[d][0];
        float p1=l1+s_jp[d][1];
        float p2=s_rot[d][6]*l0+s_rot[d][8]*l2+s_jp[d][2];
        float w0=sR[0]*p0+sR[1]*p1+sR[2]*p2+s_x[0];
        float w1=sR[3]*p0+sR[4]*p1+sR[5]*p2+s_x[1];
        float w2=sR[6]*p0+sR[7]*p1+sR[8]*p2+s_x[2];
        rp0[k]=w0; rp1[k]=w1; rp2[k]=w2;
        float u = clampf((w0+6.4f)/12.8f*255.f, 0.f, 255.f-1e-5f);
        float v = clampf((w1+6.4f)/12.8f*255.f, 0.f, 255.f-1e-5f);
        float uf=floorf(u), vf=floorf(v);
        int iu=(int)uf, iv=(int)vf;
        float fu=u-uf, fv=v-vf;
        int i00=iv*256+iu;
        float omu=1.f-fu, omv=1.f-fv;
        float z00=__ldg(zg+i00), z01=__ldg(zg+i00+1), z10=__ldg(zg+i00+256), z11=__ldg(zg+i00+257);
        float zs=(z00*omu+z01*fu)*omv+(z10*omu+z11*fu)*fv;
        float a00=__ldg(gxg+i00), a01=__ldg(gxg+i00+1), a10=__ldg(gxg+i00+256), a11=__ldg(gxg+i00+257);
        float gx=(a00*omu+a01*fu)*omv+(a10*omu+a11*fu)*fv;
        float c00=__ldg(gyg+i00), c01=__ldg(gyg+i00+1), c10=__ldg(gyg+i00+256), c11=__ldg(gyg+i00+257);
        float gy=(c00*omu+c01*fu)*omv+(c10*omu+c11*fu)*fv;
        float inr=1.f/(sqrtf(gx*gx+gy*gy+1.f)+1e-8f);
        float n0=-gx*inr, n1=-gy*inr, n2=inr;
        n0a[k]=n0;n1a[k]=n1;n2a[k]=n2;
        float dh=(w2-zs)*n2;
        dha[k]=dh;
        float ic=0.5f*(1.f+tanhf(-dh/0.03f*1.7320508075688772f));
        ica[k]=ic; icsum+=ic;
        size_t po=((size_t)b*NPTS+p)*3;
        out[O_RP+po]=w0; out[O_RP+po+1]=w1; out[O_RP+po+2]=w2;
        out[O_THR+po]=s_thr[d][0]; out[O_THR+po+1]=s_thr[d][1]; out[O_THR+po+2]=s_thr[d][2];
        out[O_IC+(size_t)b*NPTS+p]=ic;
    }

    // ---------------- reduce in_contact sum ----------------
    #pragma unroll
    for (int o=16;o;o>>=1) icsum+=__shfl_down_sync(0xffffffffu,icsum,o);
    if (lane==0) s_red[wid][0]=icsum;
    __syncthreads();
    if (tid==0){
        float t=0.f;
        #pragma unroll
        for (int w=0;w<8;w++) t+=s_red[w][0];
        float nc=fmaxf(t,1.f);
        s_nc=nc;
        s_kd=sqrtf(s_tm*5000.f/nc);
    }
    __syncthreads();

    // ---------------- phase 3: forces + local accumulation ----------------
    const float nc=s_nc, kd=s_kd;
    const float gc0=s_gcog[0],gc1=s_gcog[1],gc2=s_gcog[2];
    const float gd0=s_gdd[0],gd1=s_gdd[1],gd2=s_gdd[2];
    const float vx=s_xd[0],vy=s_xd[1],vz=s_xd[2];
    const float oxv=s_om[0],oyv=s_om[1],ozv=s_om[2];
    float aA0=0,aA1=0,aA2=0,aT0=0,aT1=0,aT2=0;
    #pragma unroll
    for (int k=0;k<PPT;k++){
        const int p=tid+k*NT;
        const int d=p>>7;
        float n0=n0a[k],n1=n1a[k],n2=n2a[k];
        float cc0=rp0[k]-gc0, cc1=rp1[k]-gc1, cc2=rp2[k]-gc2;
        float xp0=vx+oyv*cc2-ozv*cc1;
        float xp1=vy+ozv*cc0-oxv*cc2;
        float xp2=vz+oxv*cc1-oyv*cc0;
        float xdn=xp0*n0+xp1*n1+xp2*n2;
        float ic=ica[k];
        float coef=-(5000.f*dha[k]*ic+kd*xdn)*ic/nc;
        float fs0=coef*n0, fs1=coef*n1, fs2=coef*n2;
        float Nmag=sqrtf(fs0*fs0+fs1*fs1+fs2*fs2);
        float gdn=gd0*n0+gd1*n1+gd2*n2;
        float t0=gd0-gdn*n0, t1=gd1-gdn*n1, t2=gd2-gdn*n2;
        float tin=1.f/(sqrtf(t0*t0+t1*t1+t2*t2)+1e-8f);
        float f0=t0*tin, f1=t1*tin, f2=t2*tin;
        float l0=f1*n2-f2*n1, l1=f2*n0-f0*n2, l2=f0*n1-f1*n0;
        float lin=1.f/(sqrtf(l0*l0+l1*l1+l2*l2)+1e-8f);
        l0*=lin; l1*=lin; l2*=lin;
        float dv0=s_thr[d][0]-xp0, dv1=s_thr[d][1]-xp1, dv2=s_thr[d][2]-xp2;
        float dvn=dv0*n0+dv1*n1+dv2*n2;
        float dt0=tanhf(dv0-dvn*n0);
        float dt1=tanhf(dv1-dvn*n1);
        float dt2=tanhf(dv2-dvn*n2);
        float lon=dt0*f0+dt1*f1+dt2*f2;
        float lat=dt0*l0+dt1*l1+dt2*l2;
        float cf=0.5f*Nmag*lon, cl=0.5f*Nmag*lat;
        float ff0=cf*f0+cl*l0, ff1=cf*f1+cl*l1, ff2=cf*f2+cl*l2;
        float a0=fs0+ff0, a1=fs1+ff1, a2=fs2+ff2;
        aA0+=a0; aA1+=a1; aA2+=a2;
        aT0+=cc1*a2-cc2*a1;
        aT1+=cc2*a0-cc0*a2;
        aT2+=cc0*a1-cc1*a0;
        size_t po=((size_t)b*NPTS+p)*3;
        out[O_FS+po]=fs0; out[O_FS+po+1]=fs1; out[O_FS+po+2]=fs2;
        out[O_FF+po]=ff0; out[O_FF+po+1]=ff1; out[O_FF+po+2]=ff2;
    }

    // ---------------- reduce act sum + torque ----------------
    {
        float vals[6]={aA0,aA1,aA2,aT0,aT1,aT2};
        #pragma unroll
        for (int j=0;j<6;j++){
            float v=vals[j];
            #pragma unroll
            for (int o=16;o;o>>=1) v+=__shfl_down_sync(0xffffffffu,v,o);
            if (lane==0) s_red[wid][j]=v;
        }
    }
    __syncthreads();

    // ---------------- finalize (thread 0) ----------------
    if (tid==0){
        float A0=0,A1=0,A2=0,T0s=0,T1s=0,T2s=0;
        #pragma unroll
        for (int w=0;w<8;w++){
            A0+=s_red[w][0]; A1+=s_red[w][1]; A2+=s_red[w][2];
            T0s+=s_red[w][3]; T1s+=s_red[w][4]; T2s+=s_red[w][5];
        }
        float tq0=clampf(T0s,-200.f,200.f);
        float tq1=clampf(T1s,-200.f,200.f);
        float tq2=clampf(T2s,-200.f,200.f);
        float a00=s_I[0],a01=s_I[1],a02=s_I[2];
        float a10=s_I[3],a11=s_I[4],a12=s_I[5];
        float a20=s_I[6],a21=s_I[7],a22=s_I[8];
        float c00=a11*a22-a12*a21;
        float c01=a12*a20-a10*a22;
        float c02=a10*a21-a11*a20;
        float det=a00*c00+a01*c01+a02*c02;
        float inv=1.f/det;
        float wd0=(c00*tq0+(a02*a21-a01*a22)*tq1+(a01*a12-a02*a11)*tq2)*inv;
        float wd1=(c01*tq0+(a00*a22-a02*a20)*tq1+(a02*a10-a00*a12)*tq2)*inv;
        float wd2=(c02*tq0+(a01*a20-a00*a21)*tq1+(a00*a11-a01*a10)*tq2)*inv;
        float tm=s_tm;
        float xdd0=A0/tm, xdd1=A1/tm, xdd2=(A2-tm*9.8f)/tm;
        float nxd0=s_xd[0]+xdd0*0.01f, nxd1=s_xd[1]+xdd1*0.01f, nxd2=s_xd[2]+xdd2*0.01f;
        float nx0=s_x[0]+nxd0*0.01f, nx1=s_x[1]+nxd1*0.01f, nx2=s_x[2]+nxd2*0.01f;
        float no0=s_om[0]+wd0*0.01f, no1=s_om[1]+wd1*0.01f, no2=s_om[2]+wd2*0.01f;
        float qw=s_q[0],qx=s_q[1],qy=s_q[2],qz=s_q[3];
        const float hw=0.5f*0.01f;
        float dqw=hw*(-qx*no0-qy*no1-qz*no2);
        float dqx=hw*( qw*no0+qy*no2-qz*no1);
        float dqy=hw*( qw*no1-qx*no2+qz*no0);
        float dqz=hw*( qw*no2+qx*no1-qy*no0);
        float nqw=qw+dqw, nqx=qx+dqx, nqy=qy+dqy, nqz=qz+dqz;
        float qn=1.f/(sqrtf(nqw*nqw+nqx*nqx+nqy*nqy+nqz*nqz)+1e-8f);
        size_t b3=(size_t)b*3, b4=(size_t)b*4;
        out[O_NX+b3]=nx0;  out[O_NX+b3+1]=nx1;  out[O_NX+b3+2]=nx2;
        out[O_NXD+b3]=nxd0; out[O_NXD+b3+1]=nxd1; out[O_NXD+b3+2]=nxd2;
        out[O_NQ+b4]=nqw*qn; out[O_NQ+b4+1]=nqx*qn; out[O_NQ+b4+2]=nqy*qn; out[O_NQ+b4+3]=nqz*qn;
        out[O_NOM+b3]=no0; out[O_NOM+b3+1]=no1; out[O_NOM+b3+2]=no2;
        out[O_XDD+b3]=xdd0; out[O_XDD+b3+1]=xdd1; out[O_XDD+b3+2]=xdd2;
        out[O_OMD+b3]=wd0; out[O_OMD+b3+1]=wd1; out[O_OMD+b3+2]=wd2;
        out[O_TQ+b3]=tq0; out[O_TQ+b3+1]=tq1; out[O_TQ+b3+2]=tq2;
    }
}

extern "C" void kernel_launch(void* const* d_in, const int* in_sizes, int n_in,
                              void* d_out, int out_size) {
    (void)in_sizes; (void)n_in; (void)out_size;
    phys_kernel<<<NB, NT>>>(
        (const float*)d_in[0],  (const float*)d_in[1],
        (const float*)d_in[2],  (const float*)d_in[3],
        (const float*)d_in[4],  (const float*)d_in[5],
        (const float*)d_in[6],  (const float*)d_in[7],
        (const float*)d_in[8],  (const float*)d_in[9],
        (const float*)d_in[10], (const float*)d_in[11],
        (const float*)d_in[12], (const float*)d_in[13],
        (const float*)d_in[14], (const float*)d_in[15],
        (float*)d_out);
}

// round 2
// speedup vs baseline: 1.3762x; 1.3762x over previous
#include <cuda_runtime.h>
#include <math.h>

#define NB 1024
#define ND 8
#define NP 128
#define NPTS 1024
#define NT 256
#define PPT 4

// ---- output offsets (elements, f32), outputs concatenated in return order ----
#define O_NX   0u
#define O_NXD  3072u
#define O_NQ   6144u
#define O_NOM  10240u
#define O_NTH  13312u
#define O_XDD  21504u
#define O_OMD  24576u
#define O_THD  27648u
#define O_FS   35840u
#define O_FF   3181568u
#define O_IC   6327296u
#define O_TQ   7375872u
#define O_RP   7378944u
#define O_THR  10524672u
// total = 13670400

__device__ __forceinline__ float clampf(float v, float lo, float hi){
    return fminf(fmaxf(v, lo), hi);
}

// tanh via HW exp2 path: 1 - 2/(exp(2x)+1). rel err ~1e-6, handles +-inf saturation.
__device__ __forceinline__ float fast_tanh(float x){
    float e = __expf(2.0f * x);
    return 1.0f - __fdividef(2.0f, e + 1.0f);
}

__global__ __launch_bounds__(NT, 4) void phys_kernel(
    const float* __restrict__ g_x, const float* __restrict__ g_xd,
    const float* __restrict__ g_q, const float* __restrict__ g_om,
    const float* __restrict__ g_th, const float* __restrict__ g_ctl,
    const float* __restrict__ g_zg, const float* __restrict__ g_zgg,
    const float* __restrict__ g_jpos, const float* __restrict__ g_jlp,
    const float* __restrict__ g_jlc, const float* __restrict__ g_dpi,
    const float* __restrict__ g_dpm, const float* __restrict__ g_bcog,
    const float* __restrict__ g_bin, const float* __restrict__ g_dd,
    float* __restrict__ out)
{
    const int b = blockIdx.x;
    const int tid = threadIdx.x;
    const int lane = tid & 31;
    const int wid = tid >> 5;

    __shared__ float sR[9];
    __shared__ float s_rot[ND][9];
    __shared__ float s_jp[ND][3];
    __shared__ float s_thr[ND][3];
    __shared__ float s_cogl[ND][3];
    __shared__ float s_RI[ND][9];
    __shared__ float s_gcog[3], s_gdd[3], s_I[9];
    __shared__ float s_x[3], s_xd[3], s_om[3], s_q[4];
    __shared__ float s_tm, s_invnc, s_kd;
    __shared__ float s_red[8][6];

    // ---------------- phase 0: per-d precompute (threads 0..7) ----------------
    if (tid < ND) {
        const int d = tid;
        float qw=g_q[b*4+0], qx=g_q[b*4+1], qy=g_q[b*4+2], qz=g_q[b*4+3];
        float R0=1.f-2.f*(qy*qy+qz*qz), R1=2.f*(qx*qy-qw*qz), R2=2.f*(qx*qz+qw*qy);
        float R3=2.f*(qx*qy+qw*qz), R4=1.f-2.f*(qx*qx+qz*qz), R5=2.f*(qy*qz-qw*qx);
        float R6=2.f*(qx*qz-qw*qy), R7=2.f*(qy*qz+qw*qx), R8=1.f-2.f*(qx*qx+qy*qy);
        float th = g_th[b*ND+d];
        float c=cosf(th), s=sinf(th);
        float r0=c, r2=s, r6=-s, r8=c;
        s_rot[d][0]=r0; s_rot[d][1]=0.f; s_rot[d][2]=r2;
        s_rot[d][3]=0.f; s_rot[d][4]=1.f; s_rot[d][5]=0.f;
        s_rot[d][6]=r6; s_rot[d][7]=0.f; s_rot[d][8]=r8;
        float jp0=g_jpos[d*3], jp1=g_jpos[d*3+1], jp2=g_jpos[d*3+2];
        s_jp[d][0]=jp0; s_jp[d][1]=jp1; s_jp[d][2]=jp2;
        float c0=g_jlc[d*3], c1=g_jlc[d*3+1], c2=g_jlc[d*3+2];
        s_cogl[d][0]=r0*c0+r2*c2+jp0;
        s_cogl[d][1]=c1+jp1;
        s_cogl[d][2]=r6*c0+r8*c2+jp2;
        // rot * I * rot^T (rot is y-rotation; zeros contribute exactly 0)
        float I0=g_dpi[d*9+0],I1=g_dpi[d*9+1],I2=g_dpi[d*9+2];
        float I3=g_dpi[d*9+3],I4=g_dpi[d*9+4],I5=g_dpi[d*9+5];
        float I6=g_dpi[d*9+6],I7=g_dpi[d*9+7],I8=g_dpi[d*9+8];
        float T0=r0*I0+r2*I6, T1=r0*I1+r2*I7, T2=r0*I2+r2*I8;
        float T3=I3,          T4=I4,          T5=I5;
        float T6=r6*I0+r8*I6, T7=r6*I1+r8*I7, T8=r6*I2+r8*I8;
        s_RI[d][0]=T0*r0+T2*r2; s_RI[d][1]=T1;  s_RI[d][2]=T0*r6+T2*r8;
        s_RI[d][3]=T3*r0+T5*r2; s_RI[d][4]=T4;  s_RI[d][5]=T3*r6+T5*r8;
        s_RI[d][6]=T6*r0+T8*r2; s_RI[d][7]=T7;  s_RI[d][8]=T6*r6+T8*r8;
        float dd0=g_dd[0], dd1=g_dd[1], dd2=g_dd[2];
        float ctl=g_ctl[b*16+d];
        float tl0=(r0*dd0+r2*dd2)*ctl;
        float tl1=dd1*ctl;
        float tl2=(r6*dd0+r8*dd2)*ctl;
        s_thr[d][0]=R0*tl0+R1*tl1+R2*tl2;
        s_thr[d][1]=R3*tl0+R4*tl1+R5*tl2;
        s_thr[d][2]=R6*tl0+R7*tl1+R8*tl2;
        if (d==0) {
            sR[0]=R0;sR[1]=R1;sR[2]=R2;sR[3]=R3;sR[4]=R4;sR[5]=R5;sR[6]=R6;sR[7]=R7;sR[8]=R8;
            s_x[0]=g_x[b*3];s_x[1]=g_x[b*3+1];s_x[2]=g_x[b*3+2];
            s_xd[0]=g_xd[b*3];s_xd[1]=g_xd[b*3+1];s_xd[2]=g_xd[b*3+2];
            s_om[0]=g_om[b*3];s_om[1]=g_om[b*3+1];s_om[2]=g_om[b*3+2];
            s_q[0]=qw;s_q[1]=qx;s_q[2]=qy;s_q[3]=qz;
            s_gdd[0]=R0*dd0+R1*dd1+R2*dd2;
            s_gdd[1]=R3*dd0+R4*dd1+R5*dd2;
            s_gdd[2]=R6*dd0+R7*dd1+R8*dd2;
        }
        // theta outputs (independent of everything else)
        float ctl2 = g_ctl[b*16+ND+d];
        float td = clampf(ctl2, -0.5f, 0.5f);
        out[O_THD + (size_t)b*ND + d] = td;
        out[O_NTH + (size_t)b*ND + d] = clampf(th + td*0.01f, -1.f, 1.f);
    }
    __syncthreads();

    // ---------------- phase 0b: batch-level assembly (thread 0) ----------------
    if (tid == 0) {
        float m[ND]; float tm=40.f;
        float co0=0.f,co1=0.f,co2=0.f;
        #pragma unroll
        for (int d=0; d<ND; d++){
            m[d]=g_dpm[d]; tm+=m[d];
            co0+=s_cogl[d][0]*m[d]; co1+=s_cogl[d][1]*m[d]; co2+=s_cogl[d][2]*m[d];
        }
        float bc0=g_bcog[0],bc1=g_bcog[1],bc2=g_bcog[2];
        co0=(co0+40.f*bc0)/tm; co1=(co1+40.f*bc1)/tm; co2=(co2+40.f*bc2)/tm;
        float Io[9]={0,0,0,0,0,0,0,0,0};
        #pragma unroll
        for (int d=0; d<ND; d++){
            float d0=s_cogl[d][0]-co0, d1=s_cogl[d][1]-co1, d2=s_cogl[d][2]-co2;
            float ds=d0*d0+d1*d1+d2*d2;
            Io[0]+=s_RI[d][0]+m[d]*(ds-d0*d0);
            Io[1]+=s_RI[d][1]-m[d]*d0*d1;
            Io[2]+=s_RI[d][2]-m[d]*d0*d2;
            Io[3]+=s_RI[d][3]-m[d]*d0*d1;
            Io[4]+=s_RI[d][4]+m[d]*(ds-d1*d1);
            Io[5]+=s_RI[d][5]-m[d]*d1*d2;
            Io[6]+=s_RI[d][6]-m[d]*d0*d2;
            Io[7]+=s_RI[d][7]-m[d]*d1*d2;
            Io[8]+=s_RI[d][8]+m[d]*(ds-d2*d2);
        }
        float db0=bc0-co0, db1=bc1-co1, db2=bc2-co2;
        float dbs=db0*db0+db1*db1+db2*db2;
        Io[0]+=g_bin[0]+40.f*(dbs-db0*db0);
        Io[1]+=g_bin[1]-40.f*db0*db1;
        Io[2]+=g_bin[2]-40.f*db0*db2;
        Io[3]+=g_bin[3]-40.f*db0*db1;
        Io[4]+=g_bin[4]+40.f*(dbs-db1*db1);
        Io[5]+=g_bin[5]-40.f*db1*db2;
        Io[6]+=g_bin[6]-40.f*db0*db2;
        Io[7]+=g_bin[7]-40.f*db1*db2;
        Io[8]+=g_bin[8]+40.f*(dbs-db2*db2);
        // world inertia = R * Io * R^T
        float T[9];
        #pragma unroll
        for (int i=0;i<3;i++){
            T[i*3+0]=sR[i*3+0]*Io[0]+sR[i*3+1]*Io[3]+sR[i*3+2]*Io[6];
            T[i*3+1]=sR[i*3+0]*Io[1]+sR[i*3+1]*Io[4]+sR[i*3+2]*Io[7];
            T[i*3+2]=sR[i*3+0]*Io[2]+sR[i*3+1]*Io[5]+sR[i*3+2]*Io[8];
        }
        #pragma unroll
        for (int i=0;i<3;i++)
            #pragma unroll
            for (int j=0;j<3;j++)
                s_I[i*3+j]=T[i*3+0]*sR[j*3+0]+T[i*3+1]*sR[j*3+1]+T[i*3+2]*sR[j*3+2];
        s_gcog[0]=sR[0]*co0+sR[1]*co1+sR[2]*co2+s_x[0];
        s_gcog[1]=sR[3]*co0+sR[4]*co1+sR[5]*co2+s_x[1];
        s_gcog[2]=sR[6]*co0+sR[7]*co1+sR[8]*co2+s_x[2];
        s_tm=tm;
    }
    __syncthreads();

    // ---------------- phase 1: per-point geometry + contact ----------------
    float rp0[PPT],rp1[PPT],rp2[PPT];
    float n0a[PPT],n1a[PPT],n2a[PPT];
    float dha[PPT],ica[PPT];
    const float* zg  = g_zg  + (size_t)b*65536u;
    const float* gxg = g_zgg + (size_t)b*131072u;
    const float* gyg = gxg + 65536;
    float icsum=0.f;
    #pragma unroll
    for (int k=0;k<PPT;k++){
        const int p = tid + k*NT;
        const int d = p >> 7;
        const float* lp = g_jlp + ((size_t)(d*NP + (p & 127)))*3;
        float l0=__ldg(lp), l1=__ldg(lp+1), l2=__ldg(lp+2);
        float p0=s_rot[d][0]*l0+s_rot[d][2]*l2+s_jp[d][0];
        float p1=l1+s_jp[d][1];
        float p2=s_rot[d][6]*l0+s_rot[d][8]*l2+s_jp[d][2];
        float w0=sR[0]*p0+sR[1]*p1+sR[2]*p2+s_x[0];
        float w1=sR[3]*p0+sR[4]*p1+sR[5]*p2+s_x[1];
        float w2=sR[6]*p0+sR[7]*p1+sR[8]*p2+s_x[2];
        rp0[k]=w0; rp1[k]=w1; rp2[k]=w2;
        float u = clampf((w0+6.4f)*(255.f/12.8f), 0.f, 255.f-1e-5f);
        float v = clampf((w1+6.4f)*(255.f/12.8f), 0.f, 255.f-1e-5f);
        float uf=floorf(u), vf=floorf(v);
        int iu=(int)uf, iv=(int)vf;
        float fu=u-uf, fv=v-vf;
        int i00=iv*256+iu;
        float omu=1.f-fu, omv=1.f-fv;
        float z00=__ldg(zg+i00), z01=__ldg(zg+i00+1), z10=__ldg(zg+i00+256), z11=__ldg(zg+i00+257);
        float a00=__ldg(gxg+i00), a01=__ldg(gxg+i00+1), a10=__ldg(gxg+i00+256), a11=__ldg(gxg+i00+257);
        float c00=__ldg(gyg+i00), c01=__ldg(gyg+i00+1), c10=__ldg(gyg+i00+256), c11=__ldg(gyg+i00+257);
        float zs=(z00*omu+z01*fu)*omv+(z10*omu+z11*fu)*fv;
        float gx=(a00*omu+a01*fu)*omv+(a10*omu+a11*fu)*fv;
        float gy=(c00*omu+c01*fu)*omv+(c10*omu+c11*fu)*fv;
        float inr=rsqrtf(gx*gx+gy*gy+1.f);
        float n0=-gx*inr, n1=-gy*inr, n2=inr;
        n0a[k]=n0;n1a[k]=n1;n2a[k]=n2;
        float dh=(w2-zs)*n2;
        dha[k]=dh;
        float ic=0.5f*(1.f+fast_tanh(dh*-57.73502691896258f));
        ica[k]=ic; icsum+=ic;
        size_t po=((size_t)b*NPTS+p)*3;
        out[O_RP+po]=w0; out[O_RP+po+1]=w1; out[O_RP+po+2]=w2;
        out[O_THR+po]=s_thr[d][0]; out[O_THR+po+1]=s_thr[d][1]; out[O_THR+po+2]=s_thr[d][2];
        out[O_IC+(size_t)b*NPTS+p]=ic;
    }

    // ---------------- reduce in_contact sum ----------------
    #pragma unroll
    for (int o=16;o;o>>=1) icsum+=__shfl_down_sync(0xffffffffu,icsum,o);
    if (lane==0) s_red[wid][0]=icsum;
    __syncthreads();
    if (tid==0){
        float t=0.f;
        #pragma unroll
        for (int w=0;w<8;w++) t+=s_red[w][0];
        float nc=fmaxf(t,1.f);
        s_invnc=1.f/nc;
        s_kd=sqrtf(s_tm*5000.f/nc);
    }
    __syncthreads();

    // ---------------- phase 3: forces + local accumulation ----------------
    const float invnc=s_invnc, kd=s_kd;
    const float gc0=s_gcog[0],gc1=s_gcog[1],gc2=s_gcog[2];
    const float gd0=s_gdd[0],gd1=s_gdd[1],gd2=s_gdd[2];
    const float vx=s_xd[0],vy=s_xd[1],vz=s_xd[2];
    const float oxv=s_om[0],oyv=s_om[1],ozv=s_om[2];
    float aA0=0,aA1=0,aA2=0,aT0=0,aT1=0,aT2=0;
    #pragma unroll
    for (int k=0;k<PPT;k++){
        const int p=tid+k*NT;
        const int d=p>>7;
        float n0=n0a[k],n1=n1a[k],n2=n2a[k];
        float cc0=rp0[k]-gc0, cc1=rp1[k]-gc1, cc2=rp2[k]-gc2;
        float xp0=vx+oyv*cc2-ozv*cc1;
        float xp1=vy+ozv*cc0-oxv*cc2;
        float xp2=vz+oxv*cc1-oyv*cc0;
        float xdn=xp0*n0+xp1*n1+xp2*n2;
        float ic=ica[k];
        float coef=-(5000.f*dha[k]*ic+kd*xdn)*ic*invnc;
        float fs0=coef*n0, fs1=coef*n1, fs2=coef*n2;
        float Nmag=fabsf(coef)*sqrtf(n0*n0+n1*n1+n2*n2);
        float gdn=gd0*n0+gd1*n1+gd2*n2;
        float t0=gd0-gdn*n0, t1=gd1-gdn*n1, t2=gd2-gdn*n2;
        float tin=rsqrtf(t0*t0+t1*t1+t2*t2);
        float f0=t0*tin, f1=t1*tin, f2=t2*tin;
        float l0=f1*n2-f2*n1, l1=f2*n0-f0*n2, l2=f0*n1-f1*n0;
        float lin=rsqrtf(l0*l0+l1*l1+l2*l2);
        l0*=lin; l1*=lin; l2*=lin;
        float dv0=s_thr[d][0]-xp0, dv1=s_thr[d][1]-xp1, dv2=s_thr[d][2]-xp2;
        float dvn=dv0*n0+dv1*n1+dv2*n2;
        float dt0=fast_tanh(dv0-dvn*n0);
        float dt1=fast_tanh(dv1-dvn*n1);
        float dt2=fast_tanh(dv2-dvn*n2);
        float lon=dt0*f0+dt1*f1+dt2*f2;
        float lat=dt0*l0+dt1*l1+dt2*l2;
        float cf=0.5f*Nmag*lon, cl=0.5f*Nmag*lat;
        float ff0=cf*f0+cl*l0, ff1=cf*f1+cl*l1, ff2=cf*f2+cl*l2;
        float a0=fs0+ff0, a1=fs1+ff1, a2=fs2+ff2;
        aA0+=a0; aA1+=a1; aA2+=a2;
        aT0+=cc1*a2-cc2*a1;
        aT1+=cc2*a0-cc0*a2;
        aT2+=cc0*a1-cc1*a0;
        size_t po=((size_t)b*NPTS+p)*3;
        out[O_FS+po]=fs0; out[O_FS+po+1]=fs1; out[O_FS+po+2]=fs2;
        out[O_FF+po]=ff0; out[O_FF+po+1]=ff1; out[O_FF+po+2]=ff2;
    }

    // ---------------- reduce act sum + torque ----------------
    {
        float vals[6]={aA0,aA1,aA2,aT0,aT1,aT2};
        #pragma unroll
        for (int j=0;j<6;j++){
            float v=vals[j];
            #pragma unroll
            for (int o=16;o;o>>=1) v+=__shfl_down_sync(0xffffffffu,v,o);
            if (lane==0) s_red[wid][j]=v;
        }
    }
    __syncthreads();

    // ---------------- finalize (thread 0) ----------------
    if (tid==0){
        float A0=0,A1=0,A2=0,T0s=0,T1s=0,T2s=0;
        #pragma unroll
        for (int w=0;w<8;w++){
            A0+=s_red[w][0]; A1+=s_red[w][1]; A2+=s_red[w][2];
            T0s+=s_red[w][3]; T1s+=s_red[w][4]; T2s+=s_red[w][5];
        }
        float tq0=clampf(T0s,-200.f,200.f);
        float tq1=clampf(T1s,-200.f,200.f);
        float tq2=clampf(T2s,-200.f,200.f);
        float a00=s_I[0],a01=s_I[1],a02=s_I[2];
        float a10=s_I[3],a11=s_I[4],a12=s_I[5];
        float a20=s_I[6],a21=s_I[7],a22=s_I[8];
        float c00=a11*a22-a12*a21;
        float c01=a12*a20-a10*a22;
        float c02=a10*a21-a11*a20;
        float det=a00*c00+a01*c01+a02*c02;
        float inv=1.f/det;
        float wd0=(c00*tq0+(a02*a21-a01*a22)*tq1+(a01*a12-a02*a11)*tq2)*inv;
        float wd1=(c01*tq0+(a00*a22-a02*a20)*tq1+(a02*a10-a00*a12)*tq2)*inv;
        float wd2=(c02*tq0+(a01*a20-a00*a21)*tq1+(a00*a11-a01*a10)*tq2)*inv;
        float tm=s_tm;
        float xdd0=A0/tm, xdd1=A1/tm, xdd2=(A2-tm*9.8f)/tm;
        float nxd0=s_xd[0]+xdd0*0.01f, nxd1=s_xd[1]+xdd1*0.01f, nxd2=s_xd[2]+xdd2*0.01f;
        float nx0=s_x[0]+nxd0*0.01f, nx1=s_x[1]+nxd1*0.01f, nx2=s_x[2]+nxd2*0.01f;
        float no0=s_om[0]+wd0*0.01f, no1=s_om[1]+wd1*0.01f, no2=s_om[2]+wd2*0.01f;
        float qw=s_q[0],qx=s_q[1],qy=s_q[2],qz=s_q[3];
        const float hw=0.5f*0.01f;
        float dqw=hw*(-qx*no0-qy*no1-qz*no2);
        float dqx=hw*( qw*no0+qy*no2-qz*no1);
        float dqy=hw*( qw*no1-qx*no2+qz*no0);
        float dqz=hw*( qw*no2+qx*no1-qy*no0);
        float nqw=qw+dqw, nqx=qx+dqx, nqy=qy+dqy, nqz=qz+dqz;
        float qn=1.f/(sqrtf(nqw*nqw+nqx*nqx+nqy*nqy+nqz*nqz)+1e-8f);
        size_t b3=(size_t)b*3, b4=(size_t)b*4;
        out[O_NX+b3]=nx0;  out[O_NX+b3+1]=nx1;  out[O_NX+b3+2]=nx2;
        out[O_NXD+b3]=nxd0; out[O_NXD+b3+1]=nxd1; out[O_NXD+b3+2]=nxd2;
        out[O_NQ+b4]=nqw*qn; out[O_NQ+b4+1]=nqx*qn; out[O_NQ+b4+2]=nqy*qn; out[O_NQ+b4+3]=nqz*qn;
        out[O_NOM+b3]=no0; out[O_NOM+b3+1]=no1; out[O_NOM+b3+2]=no2;
        out[O_XDD+b3]=xdd0; out[O_XDD+b3+1]=xdd1; out[O_XDD+b3+2]=xdd2;
        out[O_OMD+b3]=wd0; out[O_OMD+b3+1]=wd1; out[O_OMD+b3+2]=wd2;
        out[O_TQ+b3]=tq0; out[O_TQ+b3+1]=tq1; out[O_TQ+b3+2]=tq2;
    }
}

extern "C" void kernel_launch(void* const* d_in, const int* in_sizes, int n_in,
                              void* d_out, int out_size) {
    (void)in_sizes; (void)n_in; (void)out_size;
    phys_kernel<<<NB, NT>>>(
        (const float*)d_in[0],  (const float*)d_in[1],
        (const float*)d_in[2],  (const float*)d_in[3],
        (const float*)d_in[4],  (const float*)d_in[5],
        (const float*)d_in[6],  (const float*)d_in[7],
        (const float*)d_in[8],  (const float*)d_in[9],
        (const float*)d_in[10], (const float*)d_in[11],
        (const float*)d_in[12], (const float*)d_in[13],
        (const float*)d_in[14], (const float*)d_in[15],
        (float*)d_out);
}